// round 12
// baseline (speedup 1.0000x reference)
#include <cuda_runtime.h>
#include <cuda_bf16.h>

#define NX 1024
#define NCELL 1023
#define EPSV 1e-10f
#define BLOCK_T 256
#define EVAL_MINBLK 6
#define EVAL_BLOCKS (EVAL_MINBLK * 148)   // one persistent wave at 6 blocks/SM

// Scratch (__device__ globals — allocation-free rule)
__device__ float2 g_cellx[NCELL];           // (x_i, 1/max(dx,EPS)) per cell
__device__ float2 g_celly[NCELL];
__device__ float4 g_quad[(NX - 1) * NX];    // {u00,u10,u01,u11} per cell (ix<<10 | iy)

// ---------------------------------------------------------------------------
// Builder (unchanged): blocks 0..1022 pack quad rows; blocks 1023/1024 build
// the x/y adaptive grids and emit per-cell (x_i, rdx) tables.
// ---------------------------------------------------------------------------
__device__ __forceinline__ void build_one_grid(const float* __restrict__ inc,
                                               float2* __restrict__ cells) {
    __shared__ float scum[1024];
    __shared__ float sg[1024];
    __shared__ float swarp[8];

    const int t    = threadIdx.x;       // 0..255
    const int lane = t & 31;
    const int warp = t >> 5;

    float v[4];
    #pragma unroll
    for (int j = 0; j < 4; j++) {
        int idx = 4 * t + j;
        float val = 0.0f;
        if (idx < 1023) {
            float xv = inc[idx];
            float sp = fmaxf(xv, 0.0f) + log1pf(expf(-fabsf(xv)));  // softplus
            val = fmaxf(sp, 1e-6f);
        }
        v[j] = val;
    }
    float c0 = v[0];
    float c1 = c0 + v[1];
    float c2 = c1 + v[2];
    float c3 = c2 + v[3];

    float incl = c3;
    #pragma unroll
    for (int off = 1; off < 32; off <<= 1) {
        float up = __shfl_up_sync(0xffffffff, incl, off);
        if (lane >= off) incl += up;
    }
    float thr_excl = incl - c3;
    if (lane == 31) swarp[warp] = incl;
    __syncthreads();

    if (warp == 0 && lane < 8) {
        float w = swarp[lane];
        #pragma unroll
        for (int off = 1; off < 8; off <<= 1) {
            float up = __shfl_up_sync(0xff, w, off);
            if (lane >= off) w += up;
        }
        swarp[lane] = w - swarp[lane];
    }
    __syncthreads();

    float pref = swarp[warp] + thr_excl;
    scum[4 * t + 0] = pref + c0;
    scum[4 * t + 1] = pref + c1;
    scum[4 * t + 2] = pref + c2;
    scum[4 * t + 3] = pref + c3;
    __syncthreads();

    float total = scum[1022];
    if (t == 0) sg[0] = 0.0f;
    #pragma unroll
    for (int j = 0; j < 4; j++) {
        int idx = 4 * t + j;
        if (idx < 1022)       sg[idx + 1] = scum[idx] / total;
        else if (idx == 1022) sg[1023]    = 1.0f;
    }
    __syncthreads();

    #pragma unroll
    for (int j = 0; j < 4; j++) {
        int idx = 4 * t + j;
        if (idx < NCELL) {
            float xi  = sg[idx];
            float rdx = 1.0f / fmaxf(sg[idx + 1] - xi, EPSV);
            cells[idx] = make_float2(xi, rdx);
        }
    }
}

__global__ __launch_bounds__(BLOCK_T)
void build_all(const float* __restrict__ incx,
               const float* __restrict__ incy,
               const float* __restrict__ u) {
    int bx = blockIdx.x;
    if (bx < NX - 1) {
        const float* r0 = u + bx * NX;
        const float* r1 = r0 + NX;
        float4* qrow = g_quad + (bx << 10);
        for (int iy = threadIdx.x; iy < NX - 1; iy += BLOCK_T) {
            float4 q;
            q.x = r0[iy];
            q.y = r1[iy];
            q.z = r0[iy + 1];
            q.w = r1[iy + 1];
            qrow[iy] = q;
        }
    } else if (bx == NX - 1) {
        build_one_grid(incx, g_cellx);
    } else {
        build_one_grid(incy, g_celly);
    }
}

// ---------------------------------------------------------------------------
// Eval: persistent + software-pipelined. Iteration issues locate+gather for
// group g, blends/stores group g-stride (gathers get a full loop body of
// latency slack beyond warp-level hiding). Lazy-probe locate.
// ---------------------------------------------------------------------------
__device__ __forceinline__ int locate(float x, const float2* __restrict__ sc,
                                      float& t) {
    int i = min(max(__float2int_rd(x * 1023.0f), 0), NCELL - 1);
    float2 c = sc[i];
    t = (x - c.x) * c.y;
    while (t < 0.0f && i > 0)            { c = sc[--i]; t = (x - c.x) * c.y; }
    while (t >= 1.0f && i < NCELL - 1)   { c = sc[++i]; t = (x - c.x) * c.y; }
    return i;
}

__device__ __forceinline__ float blend(float tx, float ty, float4 q) {
    float a = fmaf(tx, q.y - q.x, q.x);
    float b = fmaf(tx, q.w - q.z, q.z);
    return fmaf(ty, b - a, a);
}

__global__ __launch_bounds__(BLOCK_T, EVAL_MINBLK)
void eval_kernel(const float4* __restrict__ xe4, float2* __restrict__ out2,
                 const float2* __restrict__ xe2, float* __restrict__ outs,
                 int n) {
    __shared__ float2 scx[NCELL];
    __shared__ float2 scy[NCELL];
    for (int i = threadIdx.x; i < NCELL; i += BLOCK_T) {
        scx[i] = g_cellx[i];
        scy[i] = g_celly[i];
    }
    __syncthreads();

    const int ngroups = n >> 1;                  // 2-point groups
    const int stride  = gridDim.x * BLOCK_T;
    const int glast   = ngroups - 1;

    int g0 = blockIdx.x * BLOCK_T + threadIdx.x;
    if (g0 < ngroups) {
        // ---- pipeline prologue: fill stage for group g0 ----
        float4 a = __ldcs(&xe4[g0]);
        float tx0, ty0, tx1, ty1;
        int ix0 = locate(a.x, scx, tx0);
        int iy0 = locate(a.y, scy, ty0);
        int ix1 = locate(a.z, scx, tx1);
        int iy1 = locate(a.w, scy, ty1);
        float4 q0 = __ldg(&g_quad[(ix0 << 10) + iy0]);
        float4 q1 = __ldg(&g_quad[(ix1 << 10) + iy1]);
        int gp = g0;

        float4 anext = __ldcs(&xe4[min(g0 + stride, glast)]);

        #pragma unroll 1
        for (int g = g0 + stride; g < ngroups; g += stride) {
            // prefetch xe for the iteration after this one
            float4 afut = __ldcs(&xe4[min(g + stride, glast)]);

            // locate + issue gathers for CURRENT group g
            float ntx0, nty0, ntx1, nty1;
            int nix0 = locate(anext.x, scx, ntx0);
            int niy0 = locate(anext.y, scy, nty0);
            int nix1 = locate(anext.z, scx, ntx1);
            int niy1 = locate(anext.w, scy, nty1);
            float4 nq0 = __ldg(&g_quad[(nix0 << 10) + niy0]);
            float4 nq1 = __ldg(&g_quad[(nix1 << 10) + niy1]);

            // blend + store PREVIOUS group (its gathers are a full body old)
            float2 r;
            r.x = blend(tx0, ty0, q0);
            r.y = blend(tx1, ty1, q1);
            __stcs(&out2[gp], r);

            // shift pipeline
            gp = g;
            q0 = nq0;  q1 = nq1;
            tx0 = ntx0; ty0 = nty0; tx1 = ntx1; ty1 = nty1;
            anext = afut;
        }

        // ---- epilogue: drain last stage ----
        float2 r;
        r.x = blend(tx0, ty0, q0);
        r.y = blend(tx1, ty1, q1);
        __stcs(&out2[gp], r);
    }

    // scalar tail (never runs when n % 2 == 0, e.g. n = 8,000,000)
    int tail = (n >> 1) << 1;
    if (blockIdx.x == 0) {
        for (int i = tail + threadIdx.x; i < n; i += BLOCK_T) {
            float2 p = xe2[i];
            float tx, ty;
            int ixx = locate(p.x, scx, tx);
            int iyy = locate(p.y, scy, ty);
            float4 q = __ldg(&g_quad[(ixx << 10) + iyy]);
            outs[i] = blend(tx, ty, q);
        }
    }
}

// ---------------------------------------------------------------------------
extern "C" void kernel_launch(void* const* d_in, const int* in_sizes, int n_in,
                              void* d_out, int out_size) {
    const float* xe   = (const float*)d_in[0];
    const float* incx = (const float*)d_in[1];
    const float* incy = (const float*)d_in[2];
    const float* u    = (const float*)d_in[3];
    int n = out_size;   // 8,000,000

    build_all<<<(NX - 1) + 2, BLOCK_T>>>(incx, incy, u);

    eval_kernel<<<EVAL_BLOCKS, BLOCK_T>>>((const float4*)xe, (float2*)d_out,
                                          (const float2*)xe, (float*)d_out, n);
}